// round 6
// baseline (speedup 1.0000x reference)
#include <cuda_runtime.h>
#include <cuda_fp16.h>
#include <math.h>
#include <stdint.h>

// NeRF fused renderer, R5: 2 rays/CTA joint M=256 GEMM, A-fragments computed
// in registers (no A tile, no A LDSM), warp tile 64x64 with two N-passes.
// B (W2 fp16) staged once per CTA, padded stride (conflict-free ldmatrix).

namespace {
constexpr float NEARV = 0.1f, FARV = 4.0f, EPSV = 1e-6f;
constexpr int AS = 264;                        // B row stride in halves
constexpr int OFF_B     = 0;                   // [256k][AS] fp16 = 135168 B
constexpr int OFF_ACBC4 = 135168;              // float4[2][128]: ac,bc pairs
constexpr int OFF_HDW   = OFF_ACBC4 + 4096;    // float4[256]: Wsig,Wr0,Wr1,Wr2
constexpr int OFF_B2S   = OFF_HDW + 4096;      // float[256]
constexpr int OFF_E     = OFF_B2S + 1024;      // float[8]: 2 rays x 3 + pad
constexpr int OFF_CBUF  = OFF_E + 32;          // float[2][4][128]
constexpr int SMEM_REQ  = OFF_CBUF + 4096;     // 148512 B
}

__device__ __half g_W2h[256 * 256];            // fp16 W2 [k][j]

__global__ void prep_w2h(const float* __restrict__ W2) {
    int i = (blockIdx.x * 256 + threadIdx.x) * 4;
    float4 v = *(const float4*)(W2 + i);
    ((__half2*)g_W2h)[i / 2]     = __floats2half2_rn(v.x, v.y);
    ((__half2*)g_W2h)[i / 2 + 1] = __floats2half2_rn(v.z, v.w);
}

__device__ __forceinline__ void ldsm_x4_t(uint32_t* r, uint32_t a) {
    asm volatile("ldmatrix.sync.aligned.m8n8.x4.trans.shared.b16 {%0,%1,%2,%3}, [%4];"
                 : "=r"(r[0]), "=r"(r[1]), "=r"(r[2]), "=r"(r[3]) : "r"(a));
}
__device__ __forceinline__ void mma16816(float* c, const uint32_t* a,
                                         const uint32_t* b) {
    asm volatile(
        "mma.sync.aligned.m16n8k16.row.col.f32.f16.f16.f32 "
        "{%0,%1,%2,%3}, {%4,%5,%6,%7}, {%8,%9}, {%0,%1,%2,%3};"
        : "+f"(c[0]), "+f"(c[1]), "+f"(c[2]), "+f"(c[3])
        : "r"(a[0]), "r"(a[1]), "r"(a[2]), "r"(a[3]), "r"(b[0]), "r"(b[1]));
}
__device__ __forceinline__ uint32_t pack2(float lo, float hi) {
    __half2 h = __floats2half2_rn(lo, hi);
    return *(uint32_t*)&h;
}

__global__ __launch_bounds__(256, 1)
void nerf_mma2_kernel(const float* __restrict__ cam,
                      const float* __restrict__ rayv,
                      const float* __restrict__ W1,
                      const float* __restrict__ b1,
                      const float* __restrict__ b2,
                      const float* __restrict__ Wsig,
                      const float* __restrict__ bsig,
                      const float* __restrict__ Wrgb,
                      const float* __restrict__ brgb,
                      float* __restrict__ out)
{
    extern __shared__ char smem[];
    uint32_t smb;
    asm("{ .reg .u64 t; cvta.to.shared.u64 t, %1; cvt.u32.u64 %0, t; }"
        : "=r"(smb) : "l"(smem));

    const int tid = threadIdx.x;
    const int r0 = blockIdx.x * 2;

    // ---- geometry for both rays ----
    float dx[2], dy[2], dz[2];
    #pragma unroll
    for (int rr = 0; rr < 2; ++rr) {
        float v0 = rayv[(r0+rr)*3+0], v1 = rayv[(r0+rr)*3+1], v2 = rayv[(r0+rr)*3+2];
        float inv = rsqrtf(v0*v0 + v1*v1 + v2*v2);
        dx[rr] = v0*inv; dy[rr] = v1*inv; dz[rr] = v2*inv;
    }

    // ---- stage B (W2 fp16) into padded SMEM ----
    {
        const uint4* src = (const uint4*)g_W2h;
        #pragma unroll
        for (int it = 0; it < 32; ++it) {
            int idx = tid + it * 256;
            int row = idx >> 5, c = idx & 31;
            *(uint4*)(smem + OFF_B + (row * AS + c * 8) * 2) = src[idx];
        }
    }
    // ---- tables ----
    {
        int k = tid;
        ((float4*)(smem + OFF_HDW))[k] =
            make_float4(Wsig[k], Wrgb[k*3+0], Wrgb[k*3+1], Wrgb[k*3+2]);
        ((float*)(smem + OFF_B2S))[k] = b2[k];
    }
    if (tid < 128) {                       // k-pair tables for both rays
        int k0 = tid * 2;
        float w00 = W1[k0],     w10 = W1[256+k0],   w20 = W1[512+k0],   bb0 = b1[k0];
        float w01 = W1[k0+1],   w11 = W1[256+k0+1], w21 = W1[512+k0+1], bb1 = b1[k0+1];
        #pragma unroll
        for (int rr = 0; rr < 2; ++rr) {
            float cc0 = cam[(r0+rr)*3+0], cc1 = cam[(r0+rr)*3+1], cc2 = cam[(r0+rr)*3+2];
            float ac0 = cc0*w00 + cc1*w10 + cc2*w20 + bb0;
            float bc0 = dx[rr]*w00 + dy[rr]*w10 + dz[rr]*w20;
            float ac1 = cc0*w01 + cc1*w11 + cc2*w21 + bb1;
            float bc1 = dx[rr]*w01 + dy[rr]*w11 + dz[rr]*w21;
            ((float4*)(smem + OFF_ACBC4))[rr * 128 + tid] =
                make_float4(ac0, bc0, ac1, bc1);
        }
    }
    if (tid < 6) {                         // per-ray view-dir consts
        int rr = tid / 3, t = tid % 3;
        ((float*)(smem + OFF_E))[rr * 4 + t] =
            brgb[t] - (dx[rr] * Wrgb[(256+0)*3 + t] +
                       dy[rr] * Wrgb[(256+1)*3 + t] +
                       dz[rr] * Wrgb[(256+2)*3 + t]);
    }
    __syncthreads();

    // ---- warp mapping: 8 warps = (wm 0..3) x (wn 0..1); warp ray = wm>>1 ----
    const int w = tid >> 5, lane = tid & 31;
    const int wm = w & 3, wn = w >> 1 & 2 ? 0 : 0;  // placeholder (fixed below)
    const int wn_ = w >> 2;                          // 0..1
    const int ray = wm >> 1;
    const int q = lane & 3, rowq = lane >> 2;

    // z for this thread's 8 rows (mf 0..3 x {0,+8})
    float zr[8];
    #pragma unroll
    for (int i = 0; i < 8; ++i) {
        int m = wm * 64 + (i >> 1) * 16 + rowq + (i & 1) * 8;
        int p = m & 127;
        float t = (float)p * (1.0f / 127.0f);
        zr[i] = NEARV * (1.0f - t) + FARV * t;
    }
    const float4* acbc = (const float4*)(smem + OFF_ACBC4) + ray * 128;

    // B ldsm lane address parts
    const int krow = lane & 15, bcol = (lane >> 4) * 8;

    // head partial sums: 8 rows x 4 heads
    float s[8][4];
    #pragma unroll
    for (int i = 0; i < 8; ++i)
        #pragma unroll
        for (int h = 0; h < 4; ++h) s[i][h] = 0.0f;

    const float* b2s = (const float*)(smem + OFF_B2S);
    const float4* hdw = (const float4*)(smem + OFF_HDW);

    #pragma unroll
    for (int pp = 0; pp < 2; ++pp) {
        const int n0 = pp * 128 + wn_ * 64;
        uint32_t baddr[4];
        #pragma unroll
        for (int nf2 = 0; nf2 < 4; ++nf2)
            baddr[nf2] = smb + OFF_B + (krow * AS + n0 + nf2 * 16 + bcol) * 2;

        float acc[4][8][4];
        #pragma unroll
        for (int mf = 0; mf < 4; ++mf)
            #pragma unroll
            for (int nf = 0; nf < 8; ++nf)
                #pragma unroll
                for (int c = 0; c < 4; ++c) acc[mf][nf][c] = 0.0f;

        #pragma unroll 4
        for (int ks = 0; ks < 16; ++ks) {
            // A fragments from registers: h = relu(ac + bc*z)
            int kidx = ks * 8 + q;                  // float4 index (k pair)
            float4 lo = acbc[kidx];                 // ac,bc for k0,k0+1
            float4 hi = acbc[kidx + 4];             // ac,bc for k0+8,k0+9
            uint32_t a[4][4];
            #pragma unroll
            for (int mf = 0; mf < 4; ++mf) {
                float z0 = zr[mf * 2], z1 = zr[mf * 2 + 1];
                a[mf][0] = pack2(fmaxf(fmaf(lo.y, z0, lo.x), 0.0f),
                                 fmaxf(fmaf(lo.w, z0, lo.z), 0.0f));
                a[mf][1] = pack2(fmaxf(fmaf(lo.y, z1, lo.x), 0.0f),
                                 fmaxf(fmaf(lo.w, z1, lo.z), 0.0f));
                a[mf][2] = pack2(fmaxf(fmaf(hi.y, z0, hi.x), 0.0f),
                                 fmaxf(fmaf(hi.w, z0, hi.z), 0.0f));
                a[mf][3] = pack2(fmaxf(fmaf(hi.y, z1, hi.x), 0.0f),
                                 fmaxf(fmaf(hi.w, z1, hi.z), 0.0f));
            }
            #pragma unroll
            for (int nf2 = 0; nf2 < 4; ++nf2) {
                uint32_t b[4];
                ldsm_x4_t(b, baddr[nf2] + ks * (16 * AS * 2));
                #pragma unroll
                for (int mf = 0; mf < 4; ++mf) {
                    mma16816(acc[mf][nf2*2],     a[mf], b);
                    mma16816(acc[mf][nf2*2 + 1], a[mf], b + 2);
                }
            }
        }

        // fold this pass into head partials: relu(h2+b2) . {Wsig,Wrgb}
        #pragma unroll
        for (int nf = 0; nf < 8; ++nf) {
            int j0 = n0 + nf * 8 + q * 2;
            float bb0 = b2s[j0], bb1 = b2s[j0 + 1];
            float4 w0v = hdw[j0], w1v = hdw[j0 + 1];
            #pragma unroll
            for (int mf = 0; mf < 4; ++mf) {
                float h00 = fmaxf(acc[mf][nf][0] + bb0, 0.0f);
                float h01 = fmaxf(acc[mf][nf][1] + bb1, 0.0f);
                float h10 = fmaxf(acc[mf][nf][2] + bb0, 0.0f);
                float h11 = fmaxf(acc[mf][nf][3] + bb1, 0.0f);
                s[mf*2][0]   = fmaf(h00, w0v.x, fmaf(h01, w1v.x, s[mf*2][0]));
                s[mf*2][1]   = fmaf(h00, w0v.y, fmaf(h01, w1v.y, s[mf*2][1]));
                s[mf*2][2]   = fmaf(h00, w0v.z, fmaf(h01, w1v.z, s[mf*2][2]));
                s[mf*2][3]   = fmaf(h00, w0v.w, fmaf(h01, w1v.w, s[mf*2][3]));
                s[mf*2+1][0] = fmaf(h10, w0v.x, fmaf(h11, w1v.x, s[mf*2+1][0]));
                s[mf*2+1][1] = fmaf(h10, w0v.y, fmaf(h11, w1v.y, s[mf*2+1][1]));
                s[mf*2+1][2] = fmaf(h10, w0v.z, fmaf(h11, w1v.z, s[mf*2+1][2]));
                s[mf*2+1][3] = fmaf(h10, w0v.w, fmaf(h11, w1v.w, s[mf*2+1][3]));
            }
        }
    }

    // ---- slot reduction: red[m][slot(8, padded to 9)][head4] aliases B ----
    __syncthreads();                       // all B reads done
    float* red = (float*)(smem + OFF_B);   // 256 * 9 * 16B = 36864 B
    const int slot = wn_ * 4 + q;
    #pragma unroll
    for (int i = 0; i < 8; ++i) {
        int m = wm * 64 + (i >> 1) * 16 + rowq + (i & 1) * 8;
        *(float4*)(red + (m * 9 + slot) * 4) =
            make_float4(s[i][0], s[i][1], s[i][2], s[i][3]);
    }
    __syncthreads();

    float* cbuf = (float*)(smem + OFF_CBUF);
    {
        int m = tid;                       // 256 threads = 256 (ray,p)
        float4 t0 = *(float4*)(red + (m * 9 + 0) * 4);
        #pragma unroll
        for (int sl = 1; sl < 8; ++sl) {
            float4 t = *(float4*)(red + (m * 9 + sl) * 4);
            t0.x += t.x; t0.y += t.y; t0.z += t.z; t0.w += t.w;
        }
        int rr = m >> 7, p = m & 127;
        float sigma = fmaxf(t0.x + bsig[0], 0.0f);
        float ta = (float)p * (1.0f / 127.0f);
        float z0 = NEARV * (1.0f - ta) + FARV * ta;
        float tb = (float)(p + 1) * (1.0f / 127.0f);
        float z1 = NEARV * (1.0f - tb) + FARV * tb;
        float alpha = (p < 127) ? (1.0f - expf(-sigma * (z1 - z0))) : 1.0f;
        const float* e = (const float*)(smem + OFF_E) + rr * 4;
        float* cb = cbuf + rr * 512;
        cb[p]       = alpha;
        cb[128 + p] = 1.0f / (1.0f + expf(-(t0.y + e[0])));
        cb[256 + p] = 1.0f / (1.0f + expf(-(t0.z + e[1])));
        cb[384 + p] = 1.0f / (1.0f + expf(-(t0.w + e[2])));
    }
    __syncthreads();

    if (tid < 2) {
        const float* cb = cbuf + tid * 512;
        float T = 1.0f, o0 = 0.f, o1 = 0.f, o2 = 0.f;
        for (int sidx = 0; sidx < 128; ++sidx) {
            float a = cb[sidx];
            float wgt = a * T;
            o0 = fmaf(wgt, cb[128 + sidx], o0);
            o1 = fmaf(wgt, cb[256 + sidx], o1);
            o2 = fmaf(wgt, cb[384 + sidx], o2);
            T *= (1.0f - a + EPSV);
        }
        out[(r0 + tid) * 3 + 0] = o0;
        out[(r0 + tid) * 3 + 1] = o1;
        out[(r0 + tid) * 3 + 2] = o2;
    }
}

extern "C" void kernel_launch(void* const* d_in, const int* in_sizes, int n_in,
                              void* d_out, int out_size)
{
    const float* cam  = (const float*)d_in[0];
    const float* rayv = (const float*)d_in[1];
    const float* W1   = (const float*)d_in[2];
    const float* b1   = (const float*)d_in[3];
    const float* W2   = (const float*)d_in[4];
    const float* b2   = (const float*)d_in[5];
    const float* Wsig = (const float*)d_in[6];
    const float* bsig = (const float*)d_in[7];
    const float* Wrgb = (const float*)d_in[8];
    const float* brgb = (const float*)d_in[9];
    float* out = (float*)d_out;

    const int nrays = in_sizes[0] / 3;     // 4096

    prep_w2h<<<64, 256>>>(W2);

    cudaFuncSetAttribute(nerf_mma2_kernel,
                         cudaFuncAttributeMaxDynamicSharedMemorySize, SMEM_REQ);
    nerf_mma2_kernel<<<nrays / 2, 256, SMEM_REQ>>>(cam, rayv, W1, b1, b2,
                                                   Wsig, bsig, Wrgb, brgb, out);
}

// round 7
// speedup vs baseline: 1.1143x; 1.1143x over previous
#include <cuda_runtime.h>
#include <cuda_fp16.h>
#include <math.h>
#include <stdint.h>

// NeRF fused renderer, R6: A-fragments generated with packed fp16 math
// (__hfma2/__hmax2) from a per-(ray,ks,q) half2 table -> ~5x fewer
// non-tensor ops per k-step than R5. 2 rays/CTA joint M=256 GEMM,
// warp tile 64x64, two N-passes, B (W2 fp16) staged once per CTA.

namespace {
constexpr float NEARV = 0.1f, FARV = 4.0f, EPSV = 1e-6f;
constexpr int AS = 264;                        // B row stride in halves
constexpr int OFF_B     = 0;                   // [256k][AS] fp16 = 135168 B
constexpr int OFF_ACBC  = 135168;              // uint4[2][64]: half2 ac/bc table
constexpr int OFF_HDW   = OFF_ACBC + 2048;     // float4[256]: Wsig,Wr0,Wr1,Wr2
constexpr int OFF_B2S   = OFF_HDW + 4096;      // float[256]
constexpr int OFF_E     = OFF_B2S + 1024;      // float[8]: 2 rays x 3 + pad
constexpr int OFF_CBUF  = OFF_E + 32;          // float[2][4][128]
constexpr int SMEM_REQ  = OFF_CBUF + 4096;     // 146464 B
}

__device__ __half g_W2h[256 * 256];            // fp16 W2 [k][j]

__global__ void prep_w2h(const float* __restrict__ W2) {
    int i = (blockIdx.x * 256 + threadIdx.x) * 4;
    float4 v = *(const float4*)(W2 + i);
    ((__half2*)g_W2h)[i / 2]     = __floats2half2_rn(v.x, v.y);
    ((__half2*)g_W2h)[i / 2 + 1] = __floats2half2_rn(v.z, v.w);
}

__device__ __forceinline__ void ldsm_x4_t(uint32_t* r, uint32_t a) {
    asm volatile("ldmatrix.sync.aligned.m8n8.x4.trans.shared.b16 {%0,%1,%2,%3}, [%4];"
                 : "=r"(r[0]), "=r"(r[1]), "=r"(r[2]), "=r"(r[3]) : "r"(a));
}
__device__ __forceinline__ void mma16816(float* c, const uint32_t* a,
                                         const uint32_t* b) {
    asm volatile(
        "mma.sync.aligned.m16n8k16.row.col.f32.f16.f16.f32 "
        "{%0,%1,%2,%3}, {%4,%5,%6,%7}, {%8,%9}, {%0,%1,%2,%3};"
        : "+f"(c[0]), "+f"(c[1]), "+f"(c[2]), "+f"(c[3])
        : "r"(a[0]), "r"(a[1]), "r"(a[2]), "r"(a[3]), "r"(b[0]), "r"(b[1]));
}

__global__ __launch_bounds__(256, 1)
void nerf_mma3_kernel(const float* __restrict__ cam,
                      const float* __restrict__ rayv,
                      const float* __restrict__ W1,
                      const float* __restrict__ b1,
                      const float* __restrict__ b2,
                      const float* __restrict__ Wsig,
                      const float* __restrict__ bsig,
                      const float* __restrict__ Wrgb,
                      const float* __restrict__ brgb,
                      float* __restrict__ out)
{
    extern __shared__ char smem[];
    uint32_t smb;
    asm("{ .reg .u64 t; cvta.to.shared.u64 t, %1; cvt.u32.u64 %0, t; }"
        : "=r"(smb) : "l"(smem));

    const int tid = threadIdx.x;
    const int r0 = blockIdx.x * 2;

    // ---- geometry for both rays ----
    float dx[2], dy[2], dz[2];
    #pragma unroll
    for (int rr = 0; rr < 2; ++rr) {
        float v0 = rayv[(r0+rr)*3+0], v1 = rayv[(r0+rr)*3+1], v2 = rayv[(r0+rr)*3+2];
        float inv = rsqrtf(v0*v0 + v1*v1 + v2*v2);
        dx[rr] = v0*inv; dy[rr] = v1*inv; dz[rr] = v2*inv;
    }

    // ---- stage B (W2 fp16) into padded SMEM ----
    {
        const uint4* src = (const uint4*)g_W2h;
        #pragma unroll
        for (int it = 0; it < 32; ++it) {
            int idx = tid + it * 256;
            int row = idx >> 5, c = idx & 31;
            *(uint4*)(smem + OFF_B + (row * AS + c * 8) * 2) = src[idx];
        }
    }
    // ---- head tables ----
    {
        int k = tid;
        ((float4*)(smem + OFF_HDW))[k] =
            make_float4(Wsig[k], Wrgb[k*3+0], Wrgb[k*3+1], Wrgb[k*3+2]);
        ((float*)(smem + OFF_B2S))[k] = b2[k];
    }
    // ---- A-gen table: entry (rr, ks, q) = {ac01, bc01, ac89, bc89} half2 ----
    if (tid < 128) {
        int rr = tid >> 6, idx = tid & 63;
        int ks = idx >> 2, q = idx & 3;
        int k0 = ks * 16 + q * 2;
        float acf[4], bcf[4];
        #pragma unroll
        for (int u = 0; u < 4; ++u) {
            int k = k0 + (u >> 1) * 8 + (u & 1);
            float w0 = W1[k], w1 = W1[256 + k], w2 = W1[512 + k];
            float cc0 = cam[(r0+rr)*3+0], cc1 = cam[(r0+rr)*3+1], cc2 = cam[(r0+rr)*3+2];
            acf[u] = cc0*w0 + cc1*w1 + cc2*w2 + b1[k];
            bcf[u] = dx[rr]*w0 + dy[rr]*w1 + dz[rr]*w2;
        }
        __half2 ac01 = __floats2half2_rn(acf[0], acf[1]);
        __half2 bc01 = __floats2half2_rn(bcf[0], bcf[1]);
        __half2 ac89 = __floats2half2_rn(acf[2], acf[3]);
        __half2 bc89 = __floats2half2_rn(bcf[2], bcf[3]);
        uint4 e;
        e.x = *(uint32_t*)&ac01; e.y = *(uint32_t*)&bc01;
        e.z = *(uint32_t*)&ac89; e.w = *(uint32_t*)&bc89;
        ((uint4*)(smem + OFF_ACBC))[rr * 64 + idx] = e;
    }
    if (tid < 6) {                         // per-ray view-dir consts
        int rr = tid / 3, t = tid % 3;
        ((float*)(smem + OFF_E))[rr * 4 + t] =
            brgb[t] - (dx[rr] * Wrgb[(256+0)*3 + t] +
                       dy[rr] * Wrgb[(256+1)*3 + t] +
                       dz[rr] * Wrgb[(256+2)*3 + t]);
    }
    __syncthreads();

    // ---- warp mapping: wm 0..3 (64 rows), wn 0..1; ray = wm>>1 ----
    const int w = tid >> 5, lane = tid & 31;
    const int wm = w & 3;
    const int wn_ = w >> 2;
    const int ray = wm >> 1;
    const int q = lane & 3, rowq = lane >> 2;

    // z (duplicated half2) for this thread's 8 rows
    __half2 zz[8];
    #pragma unroll
    for (int i = 0; i < 8; ++i) {
        int m = wm * 64 + (i >> 1) * 16 + rowq + (i & 1) * 8;
        int p = m & 127;
        float t = (float)p * (1.0f / 127.0f);
        zz[i] = __float2half2_rn(NEARV * (1.0f - t) + FARV * t);
    }
    const __half2 h2zero = __float2half2_rn(0.0f);
    const uint4* actab = (const uint4*)(smem + OFF_ACBC) + ray * 64 + q;

    const int krow = lane & 15, bcol = (lane >> 4) * 8;

    float s[8][4];
    #pragma unroll
    for (int i = 0; i < 8; ++i)
        #pragma unroll
        for (int h = 0; h < 4; ++h) s[i][h] = 0.0f;

    const float* b2s = (const float*)(smem + OFF_B2S);
    const float4* hdw = (const float4*)(smem + OFF_HDW);

    #pragma unroll 1
    for (int pp = 0; pp < 2; ++pp) {
        const int n0 = pp * 128 + wn_ * 64;
        uint32_t baddr[4];
        #pragma unroll
        for (int nf2 = 0; nf2 < 4; ++nf2)
            baddr[nf2] = smb + OFF_B + (krow * AS + n0 + nf2 * 16 + bcol) * 2;

        float acc[4][8][4];
        #pragma unroll
        for (int mf = 0; mf < 4; ++mf)
            #pragma unroll
            for (int nf = 0; nf < 8; ++nf)
                #pragma unroll
                for (int c = 0; c < 4; ++c) acc[mf][nf][c] = 0.0f;

        #pragma unroll
        for (int ks = 0; ks < 16; ++ks) {
            // A fragments: h = max(fma(bc, z, ac), 0) in packed fp16
            uint4 e = actab[ks * 4];
            __half2 ac01 = *(__half2*)&e.x, bc01 = *(__half2*)&e.y;
            __half2 ac89 = *(__half2*)&e.z, bc89 = *(__half2*)&e.w;
            uint32_t a[4][4];
            #pragma unroll
            for (int mf = 0; mf < 4; ++mf) {
                __half2 h0 = __hmax2(__hfma2(bc01, zz[mf*2],   ac01), h2zero);
                __half2 h1 = __hmax2(__hfma2(bc01, zz[mf*2+1], ac01), h2zero);
                __half2 h2 = __hmax2(__hfma2(bc89, zz[mf*2],   ac89), h2zero);
                __half2 h3 = __hmax2(__hfma2(bc89, zz[mf*2+1], ac89), h2zero);
                a[mf][0] = *(uint32_t*)&h0;
                a[mf][1] = *(uint32_t*)&h1;
                a[mf][2] = *(uint32_t*)&h2;
                a[mf][3] = *(uint32_t*)&h3;
            }
            #pragma unroll
            for (int nf2 = 0; nf2 < 4; ++nf2) {
                uint32_t b[4];
                ldsm_x4_t(b, baddr[nf2] + ks * (16 * AS * 2));
                #pragma unroll
                for (int mf = 0; mf < 4; ++mf) {
                    mma16816(acc[mf][nf2*2],     a[mf], b);
                    mma16816(acc[mf][nf2*2 + 1], a[mf], b + 2);
                }
            }
        }

        // fold pass into head partials: relu(h2+b2) . {Wsig, Wrgb}
        #pragma unroll
        for (int nf = 0; nf < 8; ++nf) {
            int j0 = n0 + nf * 8 + q * 2;
            float bb0 = b2s[j0], bb1 = b2s[j0 + 1];
            float4 w0v = hdw[j0], w1v = hdw[j0 + 1];
            #pragma unroll
            for (int mf = 0; mf < 4; ++mf) {
                float h00 = fmaxf(acc[mf][nf][0] + bb0, 0.0f);
                float h01 = fmaxf(acc[mf][nf][1] + bb1, 0.0f);
                float h10 = fmaxf(acc[mf][nf][2] + bb0, 0.0f);
                float h11 = fmaxf(acc[mf][nf][3] + bb1, 0.0f);
                s[mf*2][0]   = fmaf(h00, w0v.x, fmaf(h01, w1v.x, s[mf*2][0]));
                s[mf*2][1]   = fmaf(h00, w0v.y, fmaf(h01, w1v.y, s[mf*2][1]));
                s[mf*2][2]   = fmaf(h00, w0v.z, fmaf(h01, w1v.z, s[mf*2][2]));
                s[mf*2][3]   = fmaf(h00, w0v.w, fmaf(h01, w1v.w, s[mf*2][3]));
                s[mf*2+1][0] = fmaf(h10, w0v.x, fmaf(h11, w1v.x, s[mf*2+1][0]));
                s[mf*2+1][1] = fmaf(h10, w0v.y, fmaf(h11, w1v.y, s[mf*2+1][1]));
                s[mf*2+1][2] = fmaf(h10, w0v.z, fmaf(h11, w1v.z, s[mf*2+1][2]));
                s[mf*2+1][3] = fmaf(h10, w0v.w, fmaf(h11, w1v.w, s[mf*2+1][3]));
            }
        }
    }

    // ---- slot reduction: red[m][slot(8->9 padded)][head4] aliases B ----
    __syncthreads();
    float* red = (float*)(smem + OFF_B);
    const int slot = wn_ * 4 + q;
    #pragma unroll
    for (int i = 0; i < 8; ++i) {
        int m = wm * 64 + (i >> 1) * 16 + rowq + (i & 1) * 8;
        *(float4*)(red + (m * 9 + slot) * 4) =
            make_float4(s[i][0], s[i][1], s[i][2], s[i][3]);
    }
    __syncthreads();

    float* cbuf = (float*)(smem + OFF_CBUF);
    {
        int m = tid;
        float4 t0 = *(float4*)(red + (m * 9 + 0) * 4);
        #pragma unroll
        for (int sl = 1; sl < 8; ++sl) {
            float4 t = *(float4*)(red + (m * 9 + sl) * 4);
            t0.x += t.x; t0.y += t.y; t0.z += t.z; t0.w += t.w;
        }
        int rr = m >> 7, p = m & 127;
        float sigma = fmaxf(t0.x + bsig[0], 0.0f);
        float ta = (float)p * (1.0f / 127.0f);
        float z0 = NEARV * (1.0f - ta) + FARV * ta;
        float tb = (float)(p + 1) * (1.0f / 127.0f);
        float z1 = NEARV * (1.0f - tb) + FARV * tb;
        float alpha = (p < 127) ? (1.0f - expf(-sigma * (z1 - z0))) : 1.0f;
        const float* e = (const float*)(smem + OFF_E) + rr * 4;
        float* cb = cbuf + rr * 512;
        cb[p]       = alpha;
        cb[128 + p] = 1.0f / (1.0f + expf(-(t0.y + e[0])));
        cb[256 + p] = 1.0f / (1.0f + expf(-(t0.z + e[1])));
        cb[384 + p] = 1.0f / (1.0f + expf(-(t0.w + e[2])));
    }
    __syncthreads();

    if (tid < 2) {
        const float* cb = cbuf + tid * 512;
        float T = 1.0f, o0 = 0.f, o1 = 0.f, o2 = 0.f;
        for (int sidx = 0; sidx < 128; ++sidx) {
            float a = cb[sidx];
            float wgt = a * T;
            o0 = fmaf(wgt, cb[128 + sidx], o0);
            o1 = fmaf(wgt, cb[256 + sidx], o1);
            o2 = fmaf(wgt, cb[384 + sidx], o2);
            T *= (1.0f - a + EPSV);
        }
        out[(r0 + tid) * 3 + 0] = o0;
        out[(r0 + tid) * 3 + 1] = o1;
        out[(r0 + tid) * 3 + 2] = o2;
    }
}

extern "C" void kernel_launch(void* const* d_in, const int* in_sizes, int n_in,
                              void* d_out, int out_size)
{
    const float* cam  = (const float*)d_in[0];
    const float* rayv = (const float*)d_in[1];
    const float* W1   = (const float*)d_in[2];
    const float* b1   = (const float*)d_in[3];
    const float* W2   = (const float*)d_in[4];
    const float* b2   = (const float*)d_in[5];
    const float* Wsig = (const float*)d_in[6];
    const float* bsig = (const float*)d_in[7];
    const float* Wrgb = (const float*)d_in[8];
    const float* brgb = (const float*)d_in[9];
    float* out = (float*)d_out;

    const int nrays = in_sizes[0] / 3;     // 4096

    prep_w2h<<<64, 256>>>(W2);

    cudaFuncSetAttribute(nerf_mma3_kernel,
                         cudaFuncAttributeMaxDynamicSharedMemorySize, SMEM_REQ);
    nerf_mma3_kernel<<<nrays / 2, 256, SMEM_REQ>>>(cam, rayv, W1, b1, b2,
                                                   Wsig, bsig, Wrgb, brgb, out);
}